// round 7
// baseline (speedup 1.0000x reference)
#include <cuda_runtime.h>
#include <cuda_fp16.h>
#include <math.h>
#include <stdint.h>

#define D_MODEL 1024
#define B_SZ    8
#define S_LEN   2048
#define ROWS    (B_SZ * S_LEN)   /* 16384 */

// ---------------- scratch (device globals) ----------------
__device__ __half g_h16[(size_t)ROWS * D_MODEL];
__device__ __half g_qkv16[(size_t)ROWS * 3 * D_MODEL];
__device__ __half g_sc16[(size_t)B_SZ * S_LEN * S_LEN];
__device__ float  g_x2[(size_t)ROWS * D_MODEL];
__device__ __half g_fc16[(size_t)ROWS * 4 * D_MODEL];
__device__ __half g_waT16[(size_t)3072 * 1024];
__device__ __half g_wfT16[(size_t)4096 * 1024];
__device__ __half g_wpT16[(size_t)1024 * 4096];
__device__ __half g_vt16[(size_t)1024 * 16384];

// ---------------- helpers ----------------
__device__ __forceinline__ float gelu_exact(float x) {
    return 0.5f * x * (1.0f + erff(x * 0.70710678118654752f));
}
__device__ __forceinline__ float block_sum(float v) {
    __shared__ float sh[8];
    int lane = threadIdx.x & 31, w = threadIdx.x >> 5;
    #pragma unroll
    for (int o = 16; o; o >>= 1) v += __shfl_xor_sync(0xffffffffu, v, o);
    if (lane == 0) sh[w] = v;
    __syncthreads();
    if (w == 0) {
        v = sh[lane & 7];
        #pragma unroll
        for (int o = 4; o; o >>= 1) v += __shfl_xor_sync(0xffffffffu, v, o);
        if (lane == 0) sh[0] = v;
    }
    __syncthreads();
    float r = sh[0];
    __syncthreads();
    return r;
}
__device__ __forceinline__ float block_max(float v) {
    __shared__ float sh[8];
    int lane = threadIdx.x & 31, w = threadIdx.x >> 5;
    #pragma unroll
    for (int o = 16; o; o >>= 1) v = fmaxf(v, __shfl_xor_sync(0xffffffffu, v, o));
    if (lane == 0) sh[w] = v;
    __syncthreads();
    if (w == 0) {
        v = sh[lane & 7];
        #pragma unroll
        for (int o = 4; o; o >>= 1) v = fmaxf(v, __shfl_xor_sync(0xffffffffu, v, o));
        if (lane == 0) sh[0] = v;
    }
    __syncthreads();
    float r = sh[0];
    __syncthreads();
    return r;
}
__device__ __forceinline__ void cp16(uint32_t dst_smem, const void* gptr) {
    asm volatile("cp.async.ca.shared.global [%0], [%1], 16;"
                 :: "r"(dst_smem), "l"(gptr) : "memory");
}

// ---------------- LayerNorm: fp32 in, fp16 out ----------------
__global__ void ln_kernel(const float* __restrict__ x, const float* __restrict__ w,
                          const float* __restrict__ b, __half* __restrict__ out) {
    size_t row = blockIdx.x;
    const float4* xr = (const float4*)(x + row * D_MODEL);
    float4 v = xr[threadIdx.x];
    float s  = v.x + v.y + v.z + v.w;
    float ss = v.x * v.x + v.y * v.y + v.z * v.z + v.w * v.w;
    s  = block_sum(s);
    ss = block_sum(ss);
    float mu  = s * (1.0f / D_MODEL);
    float var = ss * (1.0f / D_MODEL) - mu * mu;
    float inv = rsqrtf(var + 1e-5f);
    float4 wv = ((const float4*)w)[threadIdx.x];
    float4 bv = ((const float4*)b)[threadIdx.x];
    __half2 o0 = __floats2half2_rn((v.x - mu) * inv * wv.x + bv.x,
                                   (v.y - mu) * inv * wv.y + bv.y);
    __half2 o1 = __floats2half2_rn((v.z - mu) * inv * wv.z + bv.z,
                                   (v.w - mu) * inv * wv.w + bv.w);
    __half2* po = (__half2*)(out + row * D_MODEL + threadIdx.x * 4);
    po[0] = o0; po[1] = o1;
}

// ---------------- Softmax over fp16 row of 2048, in-place ----------------
__global__ void softmax_kernel(__half* __restrict__ sc) {
    size_t row = blockIdx.x;
    __half* p = sc + row * (size_t)S_LEN;
    uint4 raw = ((uint4*)p)[threadIdx.x];
    __half2* hp = (__half2*)&raw;
    float f[8];
    #pragma unroll
    for (int i = 0; i < 4; i++) {
        float2 t = __half22float2(hp[i]);
        f[2 * i] = t.x; f[2 * i + 1] = t.y;
    }
    float m = f[0];
    #pragma unroll
    for (int i = 1; i < 8; i++) m = fmaxf(m, f[i]);
    m = block_max(m);
    float s = 0.0f;
    #pragma unroll
    for (int i = 0; i < 8; i++) { f[i] = expf(f[i] - m); s += f[i]; }
    s = block_sum(s);
    float inv = 1.0f / s;
    #pragma unroll
    for (int i = 0; i < 4; i++)
        hp[i] = __floats2half2_rn(f[2 * i] * inv, f[2 * i + 1] * inv);
    ((uint4*)p)[threadIdx.x] = raw;
}

// ---------------- transpose: dst[c][r] = (TO)src[r][c] ----------------
template <typename TI, typename TO>
__global__ void transpose_kernel(const TI* __restrict__ src, TO* __restrict__ dst,
                                 int lds, int ldd) {
    __shared__ float t[32][33];
    int bx = blockIdx.x * 32;
    int by = blockIdx.y * 32;
    int tx = threadIdx.x, ty = threadIdx.y;
    #pragma unroll
    for (int i = 0; i < 4; i++)
        t[ty + i * 8][tx] = (float)src[(size_t)(by + ty + i * 8) * lds + bx + tx];
    __syncthreads();
    #pragma unroll
    for (int i = 0; i < 4; i++)
        dst[(size_t)(bx + ty + i * 8) * ldd + by + tx] = (TO)t[tx][ty + i * 8];
}

// =================== fp16 mma.sync GEMM, 256x128x32, 4-stage, 1 sync/iter ==
// C = act(alpha * A @ B^T + bias) (+ residual)
// A [M,K] fp16 row-major; B [N,K] fp16 row-major (K-major).
// 256 thr = 8 warps (4x2), warp tile 64x64. M mult of 256, N of 128, K of 32.
#define LDH 40                         /* 32 + 8 pad halves; 80 B row stride */
#define A_BYTES (256 * LDH * 2)        /* 20480 */
#define B_BYTES (128 * LDH * 2)        /* 10240 */
#define STAGE_BYTES (A_BYTES + B_BYTES)
#define NSTAGE 4
#define GSMEM (NSTAGE * STAGE_BYTES)   /* 122880 */

template <bool BIAS, int ACT, bool RES, bool OUT16>
__global__ __launch_bounds__(256, 1)
void hgemm(const __half* __restrict__ A, const __half* __restrict__ B,
           const float* __restrict__ bias, const float* __restrict__ res,
           void* __restrict__ Cv,
           int K, int lda, int ldb, int ldc, int ldres,
           size_t sA, size_t sB, size_t sC, size_t sR, float alpha) {
    extern __shared__ char dsm[];
    const uint32_t sbase = (uint32_t)__cvta_generic_to_shared(dsm);

    const int bn = blockIdx.x, bm = blockIdx.y, bz = blockIdx.z;
    const __half* Ab = A + sA * bz + (size_t)bm * 256 * lda;
    const __half* Bb = B + sB * bz + (size_t)bn * 128 * ldb;

    const int tid  = threadIdx.x;
    const int lane = tid & 31;
    const int warp = tid >> 5;
    const int wm   = warp >> 1;   // 0..3 -> 64-row slice
    const int wn   = warp & 1;    // 0..1 -> 64-col slice

    // ldmatrix lane byte-offsets within a tile (row stride 80B)
    const uint32_t a_off = (uint32_t)((lane & 15) * 80 + (lane >> 4) * 16);
    const uint32_t b_row = (uint32_t)(((lane >> 4) << 3) + (lane & 7));
    const uint32_t b_off = (uint32_t)(b_row * 80 + ((lane >> 3) & 1) * 16);

    float acc[4][8][4];
    #pragma unroll
    for (int i = 0; i < 4; i++)
        #pragma unroll
        for (int j = 0; j < 8; j++)
            #pragma unroll
            for (int l = 0; l < 4; l++) acc[i][j][l] = 0.0f;

    const int T = K >> 5;

    // ---- async stage: A row = tid (4 chunks), B row = tid>>1 (2 chunks) ----
    auto stage = [&](int kt, int s) {
        const int k0 = kt << 5;
        const uint32_t sa = sbase + s * STAGE_BYTES;
        const uint32_t sb = sa + A_BYTES;
        const __half* gA = Ab + (size_t)tid * lda + k0;
        const uint32_t dA = sa + tid * 80;
        #pragma unroll
        for (int c = 0; c < 4; c++) cp16(dA + c * 16, gA + c * 8);
        const __half* gB = Bb + (size_t)(tid >> 1) * ldb + k0 + (tid & 1) * 16;
        const uint32_t dB = sb + (tid >> 1) * 80 + (tid & 1) * 32;
        cp16(dB, gB);
        cp16(dB + 16, gB + 8);
    };

    // prologue: NSTAGE-1 tiles in flight
    #pragma unroll
    for (int s = 0; s < NSTAGE - 1; s++) {
        if (s < T) stage(s, s);
        asm volatile("cp.async.commit_group;" ::: "memory");
    }

    for (int kt = 0; kt < T; kt++) {
        // tile kt ready when <= NSTAGE-2 groups pending
        asm volatile("cp.async.wait_group %0;" :: "n"(NSTAGE - 2) : "memory");
        __syncthreads();
        // stage tile kt+NSTAGE-1 into slot (kt-1)%NSTAGE (freed: every warp
        // passed the sync above only after finishing compute of iter kt-1)
        {
            const int nt = kt + NSTAGE - 1;
            if (nt < T) stage(nt, nt & (NSTAGE - 1));
            asm volatile("cp.async.commit_group;" ::: "memory");
        }

        const uint32_t sa = sbase + (kt & (NSTAGE - 1)) * STAGE_BYTES;
        const uint32_t sb = sa + A_BYTES;

        #pragma unroll
        for (int ks = 0; ks < 2; ks++) {
            uint32_t a[4][4];
            #pragma unroll
            for (int am = 0; am < 4; am++) {
                uint32_t addr = sa + (uint32_t)((wm * 64 + am * 16) * 80)
                              + a_off + ks * 32;
                asm volatile(
                    "ldmatrix.sync.aligned.m8n8.x4.shared.b16 {%0,%1,%2,%3}, [%4];"
                    : "=r"(a[am][0]), "=r"(a[am][1]), "=r"(a[am][2]), "=r"(a[am][3])
                    : "r"(addr));
            }
            uint32_t b[8][2];
            #pragma unroll
            for (int t = 0; t < 4; t++) {
                uint32_t addr = sb + (uint32_t)((wn * 64 + t * 16) * 80)
                              + b_off + ks * 32;
                uint32_t r0, r1, r2, r3;
                asm volatile(
                    "ldmatrix.sync.aligned.m8n8.x4.shared.b16 {%0,%1,%2,%3}, [%4];"
                    : "=r"(r0), "=r"(r1), "=r"(r2), "=r"(r3)
                    : "r"(addr));
                b[2 * t][0] = r0; b[2 * t][1] = r1;
                b[2 * t + 1][0] = r2; b[2 * t + 1][1] = r3;
            }
            #pragma unroll
            for (int am = 0; am < 4; am++)
                #pragma unroll
                for (int an = 0; an < 8; an++) {
                    asm volatile(
                        "mma.sync.aligned.m16n8k16.row.col.f32.f16.f16.f32 "
                        "{%0,%1,%2,%3}, {%4,%5,%6,%7}, {%8,%9}, {%0,%1,%2,%3};"
                        : "+f"(acc[am][an][0]), "+f"(acc[am][an][1]),
                          "+f"(acc[am][an][2]), "+f"(acc[am][an][3])
                        : "r"(a[am][0]), "r"(a[am][1]), "r"(a[am][2]), "r"(a[am][3]),
                          "r"(b[an][0]), "r"(b[an][1]));
                }
        }
    }

    // ---- epilogue ----
    const int q  = lane >> 2;
    const int r2 = (lane & 3) * 2;
    #pragma unroll
    for (int am = 0; am < 4; am++) {
        int row0 = bm * 256 + wm * 64 + am * 16 + q;
        int row1 = row0 + 8;
        #pragma unroll
        for (int an = 0; an < 8; an++) {
            int col = bn * 128 + wn * 64 + an * 8 + r2;
            float v00 = acc[am][an][0] * alpha;
            float v01 = acc[am][an][1] * alpha;
            float v10 = acc[am][an][2] * alpha;
            float v11 = acc[am][an][3] * alpha;
            if (BIAS) {
                float2 bv = *(const float2*)(bias + col);
                v00 += bv.x; v01 += bv.y; v10 += bv.x; v11 += bv.y;
            }
            if (ACT == 1) {
                v00 = gelu_exact(v00); v01 = gelu_exact(v01);
                v10 = gelu_exact(v10); v11 = gelu_exact(v11);
            }
            if (RES) {
                float2 r0 = *(const float2*)(res + sR * bz + (size_t)row0 * ldres + col);
                float2 r1 = *(const float2*)(res + sR * bz + (size_t)row1 * ldres + col);
                v00 += r0.x; v01 += r0.y; v10 += r1.x; v11 += r1.y;
            }
            if (OUT16) {
                __half* Cb = (__half*)Cv + sC * bz;
                *(__half2*)(Cb + (size_t)row0 * ldc + col) = __floats2half2_rn(v00, v01);
                *(__half2*)(Cb + (size_t)row1 * ldc + col) = __floats2half2_rn(v10, v11);
            } else {
                float* Cb = (float*)Cv + sC * bz;
                *(float2*)(Cb + (size_t)row0 * ldc + col) = make_float2(v00, v01);
                *(float2*)(Cb + (size_t)row1 * ldc + col) = make_float2(v10, v11);
            }
        }
    }
}

// ---------------- launch ----------------
extern "C" void kernel_launch(void* const* d_in, const int* in_sizes, int n_in,
                              void* d_out, int out_size) {
    const float* x      = (const float*)d_in[0];
    const float* ln1_w  = (const float*)d_in[1];
    const float* ln1_b  = (const float*)d_in[2];
    const float* W_attn = (const float*)d_in[3];
    const float* b_attn = (const float*)d_in[4];
    const float* ln2_w  = (const float*)d_in[5];
    const float* ln2_b  = (const float*)d_in[6];
    const float* W_fc   = (const float*)d_in[7];
    const float* b_fc   = (const float*)d_in[8];
    const float* W_proj = (const float*)d_in[9];
    const float* b_proj = (const float*)d_in[10];
    float* out = (float*)d_out;

    void* p;
    cudaGetSymbolAddress(&p, g_h16);    __half* h    = (__half*)p;
    cudaGetSymbolAddress(&p, g_qkv16);  __half* qkv  = (__half*)p;
    cudaGetSymbolAddress(&p, g_sc16);   __half* sc   = (__half*)p;
    cudaGetSymbolAddress(&p, g_x2);     float*  x2   = (float*)p;
    cudaGetSymbolAddress(&p, g_fc16);   __half* fcb  = (__half*)p;
    cudaGetSymbolAddress(&p, g_waT16);  __half* waT  = (__half*)p;
    cudaGetSymbolAddress(&p, g_wfT16);  __half* wfT  = (__half*)p;
    cudaGetSymbolAddress(&p, g_wpT16);  __half* wpT  = (__half*)p;
    cudaGetSymbolAddress(&p, g_vt16);   __half* vt   = (__half*)p;

    cudaFuncSetAttribute(hgemm<true, 0, false, true>,
                         cudaFuncAttributeMaxDynamicSharedMemorySize, GSMEM);
    cudaFuncSetAttribute(hgemm<false, 0, false, true>,
                         cudaFuncAttributeMaxDynamicSharedMemorySize, GSMEM);
    cudaFuncSetAttribute(hgemm<false, 0, true, false>,
                         cudaFuncAttributeMaxDynamicSharedMemorySize, GSMEM);
    cudaFuncSetAttribute(hgemm<true, 1, false, true>,
                         cudaFuncAttributeMaxDynamicSharedMemorySize, GSMEM);
    cudaFuncSetAttribute(hgemm<true, 0, false, false>,
                         cudaFuncAttributeMaxDynamicSharedMemorySize, GSMEM);

    dim3 blk(256);
    dim3 tblk(32, 8);

    // weight transposes -> K-major fp16
    transpose_kernel<float, __half><<<dim3(96, 32), tblk>>>(W_attn, waT, 3072, 1024);
    transpose_kernel<float, __half><<<dim3(128, 32), tblk>>>(W_fc, wfT, 4096, 1024);
    transpose_kernel<float, __half><<<dim3(32, 128), tblk>>>(W_proj, wpT, 1024, 4096);

    // 1) h = LN1(x) -> fp16
    ln_kernel<<<ROWS, blk>>>(x, ln1_w, ln1_b, h);

    // 2) qkv = h @ W_attn + b_attn -> fp16 [16384,3072]
    hgemm<true, 0, false, true><<<dim3(24, 64, 1), blk, GSMEM>>>(
        h, waT, b_attn, nullptr, qkv,
        1024, 1024, 1024, 3072, 0, 0, 0, 0, 0, 1.0f);

    // V transpose: vt[d][b*2048+t] (fp16)
    transpose_kernel<__half, __half><<<dim3(32, 512), tblk>>>(qkv + 2048, vt, 3072, 16384);

    // 3) scores = (q @ k^T)/sqrt(D) -> fp16
    hgemm<false, 0, false, true><<<dim3(16, 8, 8), blk, GSMEM>>>(
        qkv, qkv + 1024, nullptr, nullptr, sc,
        1024, 3072, 3072, 2048, 0,
        (size_t)S_LEN * 3072, (size_t)S_LEN * 3072, (size_t)S_LEN * S_LEN, 0,
        0.03125f);

    // 4) softmax (fp16 in/out)
    softmax_kernel<<<ROWS, blk>>>(sc);

    // 5) x2 = x + attn @ v  -> fp32
    hgemm<false, 0, true, false><<<dim3(8, 8, 8), blk, GSMEM>>>(
        sc, vt, nullptr, x, x2,
        2048, 2048, 16384, 1024, 1024,
        (size_t)S_LEN * S_LEN, (size_t)S_LEN,
        (size_t)S_LEN * 1024, (size_t)S_LEN * 1024, 1.0f);

    // 6) h = LN2(x2) -> fp16
    ln_kernel<<<ROWS, blk>>>(x2, ln2_w, ln2_b, h);

    // 7) fc = gelu(h @ W_fc + b_fc) -> fp16 [16384,4096]
    hgemm<true, 1, false, true><<<dim3(32, 64, 1), blk, GSMEM>>>(
        h, wfT, b_fc, nullptr, fcb,
        1024, 1024, 1024, 4096, 0, 0, 0, 0, 0, 1.0f);

    // 8) out = fc @ W_proj + b_proj -> fp32 [16384,1024]
    hgemm<true, 0, false, false><<<dim3(8, 64, 1), blk, GSMEM>>>(
        fcb, wpT, b_proj, nullptr, out,
        4096, 4096, 4096, 1024, 0, 0, 0, 0, 0, 1.0f);
}

// round 8
// speedup vs baseline: 1.1057x; 1.1057x over previous
#include <cuda_runtime.h>
#include <cuda_fp16.h>
#include <math.h>
#include <stdint.h>

#define D_MODEL 1024
#define B_SZ    8
#define S_LEN   2048
#define ROWS    (B_SZ * S_LEN)   /* 16384 */

// ---------------- scratch (device globals) ----------------
__device__ __half g_h16[(size_t)ROWS * D_MODEL];
__device__ __half g_qkv16[(size_t)ROWS * 3 * D_MODEL];
__device__ __half g_sc16[(size_t)B_SZ * S_LEN * S_LEN];
__device__ float  g_x2[(size_t)ROWS * D_MODEL];
__device__ __half g_fc16[(size_t)ROWS * 4 * D_MODEL];
__device__ __half g_waT16[(size_t)3072 * 1024];
__device__ __half g_wfT16[(size_t)4096 * 1024];
__device__ __half g_wpT16[(size_t)1024 * 4096];
__device__ __half g_vt16[(size_t)1024 * 16384];

// ---------------- helpers ----------------
__device__ __forceinline__ float gelu_exact(float x) {
    return 0.5f * x * (1.0f + erff(x * 0.70710678118654752f));
}
__device__ __forceinline__ float block_sum(float v) {
    __shared__ float sh[8];
    int lane = threadIdx.x & 31, w = threadIdx.x >> 5;
    #pragma unroll
    for (int o = 16; o; o >>= 1) v += __shfl_xor_sync(0xffffffffu, v, o);
    if (lane == 0) sh[w] = v;
    __syncthreads();
    if (w == 0) {
        v = sh[lane & 7];
        #pragma unroll
        for (int o = 4; o; o >>= 1) v += __shfl_xor_sync(0xffffffffu, v, o);
        if (lane == 0) sh[0] = v;
    }
    __syncthreads();
    float r = sh[0];
    __syncthreads();
    return r;
}
__device__ __forceinline__ float block_max(float v) {
    __shared__ float sh[8];
    int lane = threadIdx.x & 31, w = threadIdx.x >> 5;
    #pragma unroll
    for (int o = 16; o; o >>= 1) v = fmaxf(v, __shfl_xor_sync(0xffffffffu, v, o));
    if (lane == 0) sh[w] = v;
    __syncthreads();
    if (w == 0) {
        v = sh[lane & 7];
        #pragma unroll
        for (int o = 4; o; o >>= 1) v = fmaxf(v, __shfl_xor_sync(0xffffffffu, v, o));
        if (lane == 0) sh[0] = v;
    }
    __syncthreads();
    float r = sh[0];
    __syncthreads();
    return r;
}
__device__ __forceinline__ void cp16(uint32_t dst_smem, const void* gptr) {
    asm volatile("cp.async.ca.shared.global [%0], [%1], 16;"
                 :: "r"(dst_smem), "l"(gptr) : "memory");
}

// ---------------- LayerNorm: fp32 in, fp16 out ----------------
__global__ void ln_kernel(const float* __restrict__ x, const float* __restrict__ w,
                          const float* __restrict__ b, __half* __restrict__ out) {
    size_t row = blockIdx.x;
    const float4* xr = (const float4*)(x + row * D_MODEL);
    float4 v = xr[threadIdx.x];
    float s  = v.x + v.y + v.z + v.w;
    float ss = v.x * v.x + v.y * v.y + v.z * v.z + v.w * v.w;
    s  = block_sum(s);
    ss = block_sum(ss);
    float mu  = s * (1.0f / D_MODEL);
    float var = ss * (1.0f / D_MODEL) - mu * mu;
    float inv = rsqrtf(var + 1e-5f);
    float4 wv = ((const float4*)w)[threadIdx.x];
    float4 bv = ((const float4*)b)[threadIdx.x];
    __half2 o0 = __floats2half2_rn((v.x - mu) * inv * wv.x + bv.x,
                                   (v.y - mu) * inv * wv.y + bv.y);
    __half2 o1 = __floats2half2_rn((v.z - mu) * inv * wv.z + bv.z,
                                   (v.w - mu) * inv * wv.w + bv.w);
    __half2* po = (__half2*)(out + row * D_MODEL + threadIdx.x * 4);
    po[0] = o0; po[1] = o1;
}

// ---------------- Softmax over fp16 row of 2048, in-place ----------------
__global__ void softmax_kernel(__half* __restrict__ sc) {
    size_t row = blockIdx.x;
    __half* p = sc + row * (size_t)S_LEN;
    uint4 raw = ((uint4*)p)[threadIdx.x];
    __half2* hp = (__half2*)&raw;
    float f[8];
    #pragma unroll
    for (int i = 0; i < 4; i++) {
        float2 t = __half22float2(hp[i]);
        f[2 * i] = t.x; f[2 * i + 1] = t.y;
    }
    float m = f[0];
    #pragma unroll
    for (int i = 1; i < 8; i++) m = fmaxf(m, f[i]);
    m = block_max(m);
    float s = 0.0f;
    #pragma unroll
    for (int i = 0; i < 8; i++) { f[i] = expf(f[i] - m); s += f[i]; }
    s = block_sum(s);
    float inv = 1.0f / s;
    #pragma unroll
    for (int i = 0; i < 4; i++)
        hp[i] = __floats2half2_rn(f[2 * i] * inv, f[2 * i + 1] * inv);
    ((uint4*)p)[threadIdx.x] = raw;
}

// ---------------- transpose: dst[c][r] = (TO)src[r][c] ----------------
template <typename TI, typename TO>
__global__ void transpose_kernel(const TI* __restrict__ src, TO* __restrict__ dst,
                                 int lds, int ldd) {
    __shared__ float t[32][33];
    int bx = blockIdx.x * 32;
    int by = blockIdx.y * 32;
    int tx = threadIdx.x, ty = threadIdx.y;
    #pragma unroll
    for (int i = 0; i < 4; i++)
        t[ty + i * 8][tx] = (float)src[(size_t)(by + ty + i * 8) * lds + bx + tx];
    __syncthreads();
    #pragma unroll
    for (int i = 0; i < 4; i++)
        dst[(size_t)(bx + ty + i * 8) * ldd + by + tx] = (TO)t[tx][ty + i * 8];
}

// =================== fp16 mma.sync GEMM, MTILE x 128 x 32, 3-stage =========
// C = act(alpha * A @ B^T + bias) (+ residual)
// A [M,K] fp16 row-major; B [N,K] fp16 row-major (K-major).
// 256 thr = 8 warps (4x2). MTILE=256: warp tile 64x64, occ 1.
//                          MTILE=128: warp tile 32x64, occ 2.
#define LDH 40                         /* 32 + 8 pad halves; 80 B row stride */
#define NSTAGE 3

template <int MTILE, bool BIAS, int ACT, bool RES, bool OUT16>
__global__ __launch_bounds__(256, MTILE == 128 ? 2 : 1)
void hgemm(const __half* __restrict__ A, const __half* __restrict__ B,
           const float* __restrict__ bias, const float* __restrict__ res,
           void* __restrict__ Cv,
           int K, int lda, int ldb, int ldc, int ldres,
           size_t sA, size_t sB, size_t sC, size_t sR, float alpha) {
    constexpr int AM = MTILE / 64;                 // m16 tiles per warp (4 or 2)
    constexpr int A_BYTES = MTILE * LDH * 2;
    constexpr int B_BYTES = 128 * LDH * 2;
    constexpr int STAGE_BYTES = A_BYTES + B_BYTES;

    extern __shared__ char dsm[];
    const uint32_t sbase = (uint32_t)__cvta_generic_to_shared(dsm);

    const int bn = blockIdx.x, bm = blockIdx.y, bz = blockIdx.z;
    const __half* Ab = A + sA * bz + (size_t)bm * MTILE * lda;
    const __half* Bb = B + sB * bz + (size_t)bn * 128 * ldb;

    const int tid  = threadIdx.x;
    const int lane = tid & 31;
    const int warp = tid >> 5;
    const int wm   = warp >> 1;   // 0..3 -> (MTILE/4)-row slice
    const int wn   = warp & 1;    // 0..1 -> 64-col slice

    // ldmatrix lane byte-offsets within a tile (row stride 80B)
    const uint32_t a_off = (uint32_t)((lane & 15) * 80 + (lane >> 4) * 16);
    const uint32_t b_row = (uint32_t)(((lane >> 4) << 3) + (lane & 7));
    const uint32_t b_off = (uint32_t)(b_row * 80 + ((lane >> 3) & 1) * 16);

    float acc[AM][8][4];
    #pragma unroll
    for (int i = 0; i < AM; i++)
        #pragma unroll
        for (int j = 0; j < 8; j++)
            #pragma unroll
            for (int l = 0; l < 4; l++) acc[i][j][l] = 0.0f;

    const int T = K >> 5;

    // ---- async stage ----
    auto stage = [&](int kt, int s) {
        const int k0 = kt << 5;
        const uint32_t sa = sbase + s * STAGE_BYTES;
        const uint32_t sb = sa + A_BYTES;
        if (MTILE == 256) {
            const __half* gA = Ab + (size_t)tid * lda + k0;
            const uint32_t dA = sa + tid * 80;
            #pragma unroll
            for (int c = 0; c < 4; c++) cp16(dA + c * 16, gA + c * 8);
        } else {
            const __half* gA = Ab + (size_t)(tid >> 1) * lda + k0 + (tid & 1) * 16;
            const uint32_t dA = sa + (tid >> 1) * 80 + (tid & 1) * 32;
            cp16(dA, gA);
            cp16(dA + 16, gA + 8);
        }
        const __half* gB = Bb + (size_t)(tid >> 1) * ldb + k0 + (tid & 1) * 16;
        const uint32_t dB = sb + (tid >> 1) * 80 + (tid & 1) * 32;
        cp16(dB, gB);
        cp16(dB + 16, gB + 8);
    };

    #pragma unroll
    for (int s = 0; s < NSTAGE; s++) {
        if (s < T) stage(s, s);
        asm volatile("cp.async.commit_group;" ::: "memory");
    }

    int buf = 0;
    for (int kt = 0; kt < T; kt++) {
        asm volatile("cp.async.wait_group %0;" :: "n"(NSTAGE - 1) : "memory");
        __syncthreads();

        const uint32_t sa = sbase + buf * STAGE_BYTES;
        const uint32_t sb = sa + A_BYTES;

        #pragma unroll
        for (int ks = 0; ks < 2; ks++) {
            uint32_t a[AM][4];
            #pragma unroll
            for (int am = 0; am < AM; am++) {
                uint32_t addr = sa + (uint32_t)((wm * (MTILE / 4) + am * 16) * 80)
                              + a_off + ks * 32;
                asm volatile(
                    "ldmatrix.sync.aligned.m8n8.x4.shared.b16 {%0,%1,%2,%3}, [%4];"
                    : "=r"(a[am][0]), "=r"(a[am][1]), "=r"(a[am][2]), "=r"(a[am][3])
                    : "r"(addr));
            }
            uint32_t b[8][2];
            #pragma unroll
            for (int t = 0; t < 4; t++) {
                uint32_t addr = sb + (uint32_t)((wn * 64 + t * 16) * 80)
                              + b_off + ks * 32;
                uint32_t r0, r1, r2, r3;
                asm volatile(
                    "ldmatrix.sync.aligned.m8n8.x4.shared.b16 {%0,%1,%2,%3}, [%4];"
                    : "=r"(r0), "=r"(r1), "=r"(r2), "=r"(r3)
                    : "r"(addr));
                b[2 * t][0] = r0; b[2 * t][1] = r1;
                b[2 * t + 1][0] = r2; b[2 * t + 1][1] = r3;
            }
            #pragma unroll
            for (int am = 0; am < AM; am++)
                #pragma unroll
                for (int an = 0; an < 8; an++) {
                    asm volatile(
                        "mma.sync.aligned.m16n8k16.row.col.f32.f16.f16.f32 "
                        "{%0,%1,%2,%3}, {%4,%5,%6,%7}, {%8,%9}, {%0,%1,%2,%3};"
                        : "+f"(acc[am][an][0]), "+f"(acc[am][an][1]),
                          "+f"(acc[am][an][2]), "+f"(acc[am][an][3])
                        : "r"(a[am][0]), "r"(a[am][1]), "r"(a[am][2]), "r"(a[am][3]),
                          "r"(b[an][0]), "r"(b[an][1]));
                }
        }
        __syncthreads();
        if (kt + NSTAGE < T) stage(kt + NSTAGE, buf);
        asm volatile("cp.async.commit_group;" ::: "memory");
        buf = (buf + 1 == NSTAGE) ? 0 : buf + 1;
    }

    // ---- epilogue ----
    const int q  = lane >> 2;
    const int r2 = (lane & 3) * 2;
    #pragma unroll
    for (int am = 0; am < AM; am++) {
        int row0 = bm * MTILE + wm * (MTILE / 4) + am * 16 + q;
        int row1 = row0 + 8;
        #pragma unroll
        for (int an = 0; an < 8; an++) {
            int col = bn * 128 + wn * 64 + an * 8 + r2;
            float v00 = acc[am][an][0] * alpha;
            float v01 = acc[am][an][1] * alpha;
            float v10 = acc[am][an][2] * alpha;
            float v11 = acc[am][an][3] * alpha;
            if (BIAS) {
                float2 bv = *(const float2*)(bias + col);
                v00 += bv.x; v01 += bv.y; v10 += bv.x; v11 += bv.y;
            }
            if (ACT == 1) {
                v00 = gelu_exact(v00); v01 = gelu_exact(v01);
                v10 = gelu_exact(v10); v11 = gelu_exact(v11);
            }
            if (RES) {
                float2 r0 = *(const float2*)(res + sR * bz + (size_t)row0 * ldres + col);
                float2 r1 = *(const float2*)(res + sR * bz + (size_t)row1 * ldres + col);
                v00 += r0.x; v01 += r0.y; v10 += r1.x; v11 += r1.y;
            }
            if (OUT16) {
                __half* Cb = (__half*)Cv + sC * bz;
                *(__half2*)(Cb + (size_t)row0 * ldc + col) = __floats2half2_rn(v00, v01);
                *(__half2*)(Cb + (size_t)row1 * ldc + col) = __floats2half2_rn(v10, v11);
            } else {
                float* Cb = (float*)Cv + sC * bz;
                *(float2*)(Cb + (size_t)row0 * ldc + col) = make_float2(v00, v01);
                *(float2*)(Cb + (size_t)row1 * ldc + col) = make_float2(v10, v11);
            }
        }
    }
}

#define GSMEM_256 (NSTAGE * (256 * LDH * 2 + 128 * LDH * 2))  /* 92160 */
#define GSMEM_128 (NSTAGE * (128 * LDH * 2 + 128 * LDH * 2))  /* 61440 */

// ---------------- launch ----------------
extern "C" void kernel_launch(void* const* d_in, const int* in_sizes, int n_in,
                              void* d_out, int out_size) {
    const float* x      = (const float*)d_in[0];
    const float* ln1_w  = (const float*)d_in[1];
    const float* ln1_b  = (const float*)d_in[2];
    const float* W_attn = (const float*)d_in[3];
    const float* b_attn = (const float*)d_in[4];
    const float* ln2_w  = (const float*)d_in[5];
    const float* ln2_b  = (const float*)d_in[6];
    const float* W_fc   = (const float*)d_in[7];
    const float* b_fc   = (const float*)d_in[8];
    const float* W_proj = (const float*)d_in[9];
    const float* b_proj = (const float*)d_in[10];
    float* out = (float*)d_out;

    void* p;
    cudaGetSymbolAddress(&p, g_h16);    __half* h    = (__half*)p;
    cudaGetSymbolAddress(&p, g_qkv16);  __half* qkv  = (__half*)p;
    cudaGetSymbolAddress(&p, g_sc16);   __half* sc   = (__half*)p;
    cudaGetSymbolAddress(&p, g_x2);     float*  x2   = (float*)p;
    cudaGetSymbolAddress(&p, g_fc16);   __half* fcb  = (__half*)p;
    cudaGetSymbolAddress(&p, g_waT16);  __half* waT  = (__half*)p;
    cudaGetSymbolAddress(&p, g_wfT16);  __half* wfT  = (__half*)p;
    cudaGetSymbolAddress(&p, g_wpT16);  __half* wpT  = (__half*)p;
    cudaGetSymbolAddress(&p, g_vt16);   __half* vt   = (__half*)p;

    cudaFuncSetAttribute(hgemm<256, true, 0, false, true>,
                         cudaFuncAttributeMaxDynamicSharedMemorySize, GSMEM_256);
    cudaFuncSetAttribute(hgemm<256, false, 0, false, true>,
                         cudaFuncAttributeMaxDynamicSharedMemorySize, GSMEM_256);
    cudaFuncSetAttribute(hgemm<256, true, 1, false, true>,
                         cudaFuncAttributeMaxDynamicSharedMemorySize, GSMEM_256);
    cudaFuncSetAttribute(hgemm<128, false, 0, true, false>,
                         cudaFuncAttributeMaxDynamicSharedMemorySize, GSMEM_128);
    cudaFuncSetAttribute(hgemm<128, true, 0, false, false>,
                         cudaFuncAttributeMaxDynamicSharedMemorySize, GSMEM_128);

    dim3 blk(256);
    dim3 tblk(32, 8);

    // weight transposes -> K-major fp16
    transpose_kernel<float, __half><<<dim3(96, 32), tblk>>>(W_attn, waT, 3072, 1024);
    transpose_kernel<float, __half><<<dim3(128, 32), tblk>>>(W_fc, wfT, 4096, 1024);
    transpose_kernel<float, __half><<<dim3(32, 128), tblk>>>(W_proj, wpT, 1024, 4096);

    // 1) h = LN1(x) -> fp16
    ln_kernel<<<ROWS, blk>>>(x, ln1_w, ln1_b, h);

    // 2) qkv = h @ W_attn + b_attn -> fp16 [16384,3072]
    hgemm<256, true, 0, false, true><<<dim3(24, 64, 1), blk, GSMEM_256>>>(
        h, waT, b_attn, nullptr, qkv,
        1024, 1024, 1024, 3072, 0, 0, 0, 0, 0, 1.0f);

    // V transpose: vt[d][b*2048+t] (fp16)
    transpose_kernel<__half, __half><<<dim3(32, 512), tblk>>>(qkv + 2048, vt, 3072, 16384);

    // 3) scores = (q @ k^T)/sqrt(D) -> fp16
    hgemm<256, false, 0, false, true><<<dim3(16, 8, 8), blk, GSMEM_256>>>(
        qkv, qkv + 1024, nullptr, nullptr, sc,
        1024, 3072, 3072, 2048, 0,
        (size_t)S_LEN * 3072, (size_t)S_LEN * 3072, (size_t)S_LEN * S_LEN, 0,
        0.03125f);

    // 4) softmax (fp16 in/out)
    softmax_kernel<<<ROWS, blk>>>(sc);

    // 5) x2 = x + attn @ v  -> fp32   (128-tile: better tail, occ 2)
    hgemm<128, false, 0, true, false><<<dim3(8, 16, 8), blk, GSMEM_128>>>(
        sc, vt, nullptr, x, x2,
        2048, 2048, 16384, 1024, 1024,
        (size_t)S_LEN * S_LEN, (size_t)S_LEN,
        (size_t)S_LEN * 1024, (size_t)S_LEN * 1024, 1.0f);

    // 6) h = LN2(x2) -> fp16
    ln_kernel<<<ROWS, blk>>>(x2, ln2_w, ln2_b, h);

    // 7) fc = gelu(h @ W_fc + b_fc) -> fp16 [16384,4096]
    hgemm<256, true, 1, false, true><<<dim3(32, 64, 1), blk, GSMEM_256>>>(
        h, wfT, b_fc, nullptr, fcb,
        1024, 1024, 1024, 4096, 0, 0, 0, 0, 0, 1.0f);

    // 8) out = fc @ W_proj + b_proj -> fp32 [16384,1024]  (128-tile)
    hgemm<128, true, 0, false, false><<<dim3(8, 128, 1), blk, GSMEM_128>>>(
        fcb, wpT, b_proj, nullptr, out,
        4096, 4096, 4096, 1024, 0, 0, 0, 0, 0, 1.0f);
}

// round 9
// speedup vs baseline: 1.1736x; 1.0614x over previous
#include <cuda_runtime.h>
#include <cuda_fp16.h>
#include <math.h>
#include <stdint.h>

#define D_MODEL 1024
#define B_SZ    8
#define S_LEN   2048
#define ROWS    (B_SZ * S_LEN)   /* 16384 */

// ---------------- scratch (device globals) ----------------
__device__ __half g_h16[(size_t)ROWS * D_MODEL];
__device__ __half g_qkv16[(size_t)ROWS * 3 * D_MODEL];
__device__ __half g_sc16[(size_t)B_SZ * S_LEN * S_LEN];
__device__ float  g_x2[(size_t)ROWS * D_MODEL];
__device__ __half g_fc16[(size_t)ROWS * 4 * D_MODEL];
__device__ __half g_waT16[(size_t)3072 * 1024];
__device__ __half g_wfT16[(size_t)4096 * 1024];
__device__ __half g_wpT16[(size_t)1024 * 4096];
__device__ __half g_vt16[(size_t)1024 * 16384];

// ---------------- helpers ----------------
__device__ __forceinline__ float gelu_exact(float x) {
    return 0.5f * x * (1.0f + erff(x * 0.70710678118654752f));
}
__device__ __forceinline__ float block_sum(float v) {
    __shared__ float sh[8];
    int lane = threadIdx.x & 31, w = threadIdx.x >> 5;
    #pragma unroll
    for (int o = 16; o; o >>= 1) v += __shfl_xor_sync(0xffffffffu, v, o);
    if (lane == 0) sh[w] = v;
    __syncthreads();
    if (w == 0) {
        v = sh[lane & 7];
        #pragma unroll
        for (int o = 4; o; o >>= 1) v += __shfl_xor_sync(0xffffffffu, v, o);
        if (lane == 0) sh[0] = v;
    }
    __syncthreads();
    float r = sh[0];
    __syncthreads();
    return r;
}
__device__ __forceinline__ float block_max(float v) {
    __shared__ float sh[8];
    int lane = threadIdx.x & 31, w = threadIdx.x >> 5;
    #pragma unroll
    for (int o = 16; o; o >>= 1) v = fmaxf(v, __shfl_xor_sync(0xffffffffu, v, o));
    if (lane == 0) sh[w] = v;
    __syncthreads();
    if (w == 0) {
        v = sh[lane & 7];
        #pragma unroll
        for (int o = 4; o; o >>= 1) v = fmaxf(v, __shfl_xor_sync(0xffffffffu, v, o));
        if (lane == 0) sh[0] = v;
    }
    __syncthreads();
    float r = sh[0];
    __syncthreads();
    return r;
}
__device__ __forceinline__ void cp16(uint32_t dst_smem, const void* gptr) {
    asm volatile("cp.async.ca.shared.global [%0], [%1], 16;"
                 :: "r"(dst_smem), "l"(gptr) : "memory");
}

// ---------------- LayerNorm: fp32 in, fp16 out ----------------
__global__ void ln_kernel(const float* __restrict__ x, const float* __restrict__ w,
                          const float* __restrict__ b, __half* __restrict__ out) {
    size_t row = blockIdx.x;
    const float4* xr = (const float4*)(x + row * D_MODEL);
    float4 v = xr[threadIdx.x];
    float s  = v.x + v.y + v.z + v.w;
    float ss = v.x * v.x + v.y * v.y + v.z * v.z + v.w * v.w;
    s  = block_sum(s);
    ss = block_sum(ss);
    float mu  = s * (1.0f / D_MODEL);
    float var = ss * (1.0f / D_MODEL) - mu * mu;
    float inv = rsqrtf(var + 1e-5f);
    float4 wv = ((const float4*)w)[threadIdx.x];
    float4 bv = ((const float4*)b)[threadIdx.x];
    __half2 o0 = __floats2half2_rn((v.x - mu) * inv * wv.x + bv.x,
                                   (v.y - mu) * inv * wv.y + bv.y);
    __half2 o1 = __floats2half2_rn((v.z - mu) * inv * wv.z + bv.z,
                                   (v.w - mu) * inv * wv.w + bv.w);
    __half2* po = (__half2*)(out + row * D_MODEL + threadIdx.x * 4);
    po[0] = o0; po[1] = o1;
}

// ---------------- Softmax over fp16 row of 2048, in-place ----------------
__global__ void softmax_kernel(__half* __restrict__ sc) {
    size_t row = blockIdx.x;
    __half* p = sc + row * (size_t)S_LEN;
    uint4 raw = ((uint4*)p)[threadIdx.x];
    __half2* hp = (__half2*)&raw;
    float f[8];
    #pragma unroll
    for (int i = 0; i < 4; i++) {
        float2 t = __half22float2(hp[i]);
        f[2 * i] = t.x; f[2 * i + 1] = t.y;
    }
    float m = f[0];
    #pragma unroll
    for (int i = 1; i < 8; i++) m = fmaxf(m, f[i]);
    m = block_max(m);
    float s = 0.0f;
    #pragma unroll
    for (int i = 0; i < 8; i++) { f[i] = expf(f[i] - m); s += f[i]; }
    s = block_sum(s);
    float inv = 1.0f / s;
    #pragma unroll
    for (int i = 0; i < 4; i++)
        hp[i] = __floats2half2_rn(f[2 * i] * inv, f[2 * i + 1] * inv);
    ((uint4*)p)[threadIdx.x] = raw;
}

// ---------------- transpose: dst[c][r] = (TO)src[r][c] ----------------
template <typename TI, typename TO>
__global__ void transpose_kernel(const TI* __restrict__ src, TO* __restrict__ dst,
                                 int lds, int ldd) {
    __shared__ float t[32][33];
    int bx = blockIdx.x * 32;
    int by = blockIdx.y * 32;
    int tx = threadIdx.x, ty = threadIdx.y;
    #pragma unroll
    for (int i = 0; i < 4; i++)
        t[ty + i * 8][tx] = (float)src[(size_t)(by + ty + i * 8) * lds + bx + tx];
    __syncthreads();
    #pragma unroll
    for (int i = 0; i < 4; i++)
        dst[(size_t)(bx + ty + i * 8) * ldd + by + tx] = (TO)t[tx][ty + i * 8];
}

// =================== fp16 mma.sync GEMM, 128x128x32, 3-stage, occ 2 ========
// C = act(alpha * A @ B^T + bias) (+ residual)
// A [M,K] fp16 row-major; B [N,K] fp16 row-major (K-major).
// 256 thr = 8 warps (4x2), warp tile 32x64. M,N mult of 128; K of 32.
#define LDH 40                         /* 32 + 8 pad halves; 80 B row stride */
#define NSTAGE 3
#define A_BYTES (128 * LDH * 2)        /* 10240 */
#define B_BYTES (128 * LDH * 2)        /* 10240 */
#define STAGE_BYTES (A_BYTES + B_BYTES)
#define GSMEM (NSTAGE * STAGE_BYTES)   /* 61440 */

template <bool BIAS, int ACT, bool RES, bool OUT16>
__global__ __launch_bounds__(256, 2)
void hgemm(const __half* __restrict__ A, const __half* __restrict__ B,
           const float* __restrict__ bias, const float* __restrict__ res,
           void* __restrict__ Cv,
           int K, int lda, int ldb, int ldc, int ldres,
           size_t sA, size_t sB, size_t sC, size_t sR, float alpha) {
    extern __shared__ char dsm[];
    const uint32_t sbase = (uint32_t)__cvta_generic_to_shared(dsm);

    const int bn = blockIdx.x, bm = blockIdx.y, bz = blockIdx.z;
    const __half* Ab = A + sA * bz + (size_t)bm * 128 * lda;
    const __half* Bb = B + sB * bz + (size_t)bn * 128 * ldb;

    const int tid  = threadIdx.x;
    const int lane = tid & 31;
    const int warp = tid >> 5;
    const int wm   = warp >> 1;   // 0..3 -> 32-row slice
    const int wn   = warp & 1;    // 0..1 -> 64-col slice

    // ldmatrix lane byte-offsets within a tile (row stride 80B)
    const uint32_t a_off = (uint32_t)((lane & 15) * 80 + (lane >> 4) * 16);
    const uint32_t b_row = (uint32_t)(((lane >> 4) << 3) + (lane & 7));
    const uint32_t b_off = (uint32_t)(b_row * 80 + ((lane >> 3) & 1) * 16);

    float acc[2][8][4];
    #pragma unroll
    for (int i = 0; i < 2; i++)
        #pragma unroll
        for (int j = 0; j < 8; j++)
            #pragma unroll
            for (int l = 0; l < 4; l++) acc[i][j][l] = 0.0f;

    const int T = K >> 5;

    // ---- async stage: row = tid>>1, 2 chunks of 16B at (tid&1)*16 ----
    auto stage = [&](int kt, int s) {
        const int k0 = kt << 5;
        const uint32_t sa = sbase + s * STAGE_BYTES;
        const uint32_t sb = sa + A_BYTES;
        const __half* gA = Ab + (size_t)(tid >> 1) * lda + k0 + (tid & 1) * 16;
        const uint32_t dA = sa + (tid >> 1) * 80 + (tid & 1) * 32;
        cp16(dA, gA);
        cp16(dA + 16, gA + 8);
        const __half* gB = Bb + (size_t)(tid >> 1) * ldb + k0 + (tid & 1) * 16;
        const uint32_t dB = sb + (tid >> 1) * 80 + (tid & 1) * 32;
        cp16(dB, gB);
        cp16(dB + 16, gB + 8);
    };

    #pragma unroll
    for (int s = 0; s < NSTAGE; s++) {
        if (s < T) stage(s, s);
        asm volatile("cp.async.commit_group;" ::: "memory");
    }

    int buf = 0;
    for (int kt = 0; kt < T; kt++) {
        asm volatile("cp.async.wait_group %0;" :: "n"(NSTAGE - 1) : "memory");
        __syncthreads();

        const uint32_t sa = sbase + buf * STAGE_BYTES;
        const uint32_t sb = sa + A_BYTES;

        #pragma unroll
        for (int ks = 0; ks < 2; ks++) {
            uint32_t a[2][4];
            #pragma unroll
            for (int am = 0; am < 2; am++) {
                uint32_t addr = sa + (uint32_t)((wm * 32 + am * 16) * 80)
                              + a_off + ks * 32;
                asm volatile(
                    "ldmatrix.sync.aligned.m8n8.x4.shared.b16 {%0,%1,%2,%3}, [%4];"
                    : "=r"(a[am][0]), "=r"(a[am][1]), "=r"(a[am][2]), "=r"(a[am][3])
                    : "r"(addr));
            }
            uint32_t b[8][2];
            #pragma unroll
            for (int t = 0; t < 4; t++) {
                uint32_t addr = sb + (uint32_t)((wn * 64 + t * 16) * 80)
                              + b_off + ks * 32;
                uint32_t r0, r1, r2, r3;
                asm volatile(
                    "ldmatrix.sync.aligned.m8n8.x4.shared.b16 {%0,%1,%2,%3}, [%4];"
                    : "=r"(r0), "=r"(r1), "=r"(r2), "=r"(r3)
                    : "r"(addr));
                b[2 * t][0] = r0; b[2 * t][1] = r1;
                b[2 * t + 1][0] = r2; b[2 * t + 1][1] = r3;
            }
            #pragma unroll
            for (int am = 0; am < 2; am++)
                #pragma unroll
                for (int an = 0; an < 8; an++) {
                    asm volatile(
                        "mma.sync.aligned.m16n8k16.row.col.f32.f16.f16.f32 "
                        "{%0,%1,%2,%3}, {%4,%5,%6,%7}, {%8,%9}, {%0,%1,%2,%3};"
                        : "+f"(acc[am][an][0]), "+f"(acc[am][an][1]),
                          "+f"(acc[am][an][2]), "+f"(acc[am][an][3])
                        : "r"(a[am][0]), "r"(a[am][1]), "r"(a[am][2]), "r"(a[am][3]),
                          "r"(b[an][0]), "r"(b[an][1]));
                }
        }
        __syncthreads();
        if (kt + NSTAGE < T) stage(kt + NSTAGE, buf);
        asm volatile("cp.async.commit_group;" ::: "memory");
        buf = (buf + 1 == NSTAGE) ? 0 : buf + 1;
    }

    // ---- epilogue ----
    const int q  = lane >> 2;
    const int r2 = (lane & 3) * 2;
    #pragma unroll
    for (int am = 0; am < 2; am++) {
        int row0 = bm * 128 + wm * 32 + am * 16 + q;
        int row1 = row0 + 8;
        #pragma unroll
        for (int an = 0; an < 8; an++) {
            int col = bn * 128 + wn * 64 + an * 8 + r2;
            float v00 = acc[am][an][0] * alpha;
            float v01 = acc[am][an][1] * alpha;
            float v10 = acc[am][an][2] * alpha;
            float v11 = acc[am][an][3] * alpha;
            if (BIAS) {
                float2 bv = *(const float2*)(bias + col);
                v00 += bv.x; v01 += bv.y; v10 += bv.x; v11 += bv.y;
            }
            if (ACT == 1) {
                v00 = gelu_exact(v00); v01 = gelu_exact(v01);
                v10 = gelu_exact(v10); v11 = gelu_exact(v11);
            }
            if (RES) {
                float2 r0 = *(const float2*)(res + sR * bz + (size_t)row0 * ldres + col);
                float2 r1 = *(const float2*)(res + sR * bz + (size_t)row1 * ldres + col);
                v00 += r0.x; v01 += r0.y; v10 += r1.x; v11 += r1.y;
            }
            if (OUT16) {
                __half* Cb = (__half*)Cv + sC * bz;
                *(__half2*)(Cb + (size_t)row0 * ldc + col) = __floats2half2_rn(v00, v01);
                *(__half2*)(Cb + (size_t)row1 * ldc + col) = __floats2half2_rn(v10, v11);
            } else {
                float* Cb = (float*)Cv + sC * bz;
                *(float2*)(Cb + (size_t)row0 * ldc + col) = make_float2(v00, v01);
                *(float2*)(Cb + (size_t)row1 * ldc + col) = make_float2(v10, v11);
            }
        }
    }
}

// ---------------- launch ----------------
extern "C" void kernel_launch(void* const* d_in, const int* in_sizes, int n_in,
                              void* d_out, int out_size) {
    const float* x      = (const float*)d_in[0];
    const float* ln1_w  = (const float*)d_in[1];
    const float* ln1_b  = (const float*)d_in[2];
    const float* W_attn = (const float*)d_in[3];
    const float* b_attn = (const float*)d_in[4];
    const float* ln2_w  = (const float*)d_in[5];
    const float* ln2_b  = (const float*)d_in[6];
    const float* W_fc   = (const float*)d_in[7];
    const float* b_fc   = (const float*)d_in[8];
    const float* W_proj = (const float*)d_in[9];
    const float* b_proj = (const float*)d_in[10];
    float* out = (float*)d_out;

    void* p;
    cudaGetSymbolAddress(&p, g_h16);    __half* h    = (__half*)p;
    cudaGetSymbolAddress(&p, g_qkv16);  __half* qkv  = (__half*)p;
    cudaGetSymbolAddress(&p, g_sc16);   __half* sc   = (__half*)p;
    cudaGetSymbolAddress(&p, g_x2);     float*  x2   = (float*)p;
    cudaGetSymbolAddress(&p, g_fc16);   __half* fcb  = (__half*)p;
    cudaGetSymbolAddress(&p, g_waT16);  __half* waT  = (__half*)p;
    cudaGetSymbolAddress(&p, g_wfT16);  __half* wfT  = (__half*)p;
    cudaGetSymbolAddress(&p, g_wpT16);  __half* wpT  = (__half*)p;
    cudaGetSymbolAddress(&p, g_vt16);   __half* vt   = (__half*)p;

    cudaFuncSetAttribute(hgemm<true, 0, false, true>,
                         cudaFuncAttributeMaxDynamicSharedMemorySize, GSMEM);
    cudaFuncSetAttribute(hgemm<false, 0, false, true>,
                         cudaFuncAttributeMaxDynamicSharedMemorySize, GSMEM);
    cudaFuncSetAttribute(hgemm<false, 0, true, false>,
                         cudaFuncAttributeMaxDynamicSharedMemorySize, GSMEM);
    cudaFuncSetAttribute(hgemm<true, 1, false, true>,
                         cudaFuncAttributeMaxDynamicSharedMemorySize, GSMEM);
    cudaFuncSetAttribute(hgemm<true, 0, false, false>,
                         cudaFuncAttributeMaxDynamicSharedMemorySize, GSMEM);

    dim3 blk(256);
    dim3 tblk(32, 8);

    // weight transposes -> K-major fp16
    transpose_kernel<float, __half><<<dim3(96, 32), tblk>>>(W_attn, waT, 3072, 1024);
    transpose_kernel<float, __half><<<dim3(128, 32), tblk>>>(W_fc, wfT, 4096, 1024);
    transpose_kernel<float, __half><<<dim3(32, 128), tblk>>>(W_proj, wpT, 1024, 4096);

    // 1) h = LN1(x) -> fp16
    ln_kernel<<<ROWS, blk>>>(x, ln1_w, ln1_b, h);

    // 2) qkv = h @ W_attn + b_attn -> fp16 [16384,3072]
    hgemm<true, 0, false, true><<<dim3(24, 128, 1), blk, GSMEM>>>(
        h, waT, b_attn, nullptr, qkv,
        1024, 1024, 1024, 3072, 0, 0, 0, 0, 0, 1.0f);

    // V transpose: vt[d][b*2048+t] (fp16)
    transpose_kernel<__half, __half><<<dim3(32, 512), tblk>>>(qkv + 2048, vt, 3072, 16384);

    // 3) scores = (q @ k^T)/sqrt(D) -> fp16
    hgemm<false, 0, false, true><<<dim3(16, 16, 8), blk, GSMEM>>>(
        qkv, qkv + 1024, nullptr, nullptr, sc,
        1024, 3072, 3072, 2048, 0,
        (size_t)S_LEN * 3072, (size_t)S_LEN * 3072, (size_t)S_LEN * S_LEN, 0,
        0.03125f);

    // 4) softmax (fp16 in/out)
    softmax_kernel<<<ROWS, blk>>>(sc);

    // 5) x2 = x + attn @ v  -> fp32
    hgemm<false, 0, true, false><<<dim3(8, 16, 8), blk, GSMEM>>>(
        sc, vt, nullptr, x, x2,
        2048, 2048, 16384, 1024, 1024,
        (size_t)S_LEN * S_LEN, (size_t)S_LEN,
        (size_t)S_LEN * 1024, (size_t)S_LEN * 1024, 1.0f);

    // 6) h = LN2(x2) -> fp16
    ln_kernel<<<ROWS, blk>>>(x2, ln2_w, ln2_b, h);

    // 7) fc = gelu(h @ W_fc + b_fc) -> fp16 [16384,4096]
    hgemm<true, 1, false, true><<<dim3(32, 128, 1), blk, GSMEM>>>(
        h, wfT, b_fc, nullptr, fcb,
        1024, 1024, 1024, 4096, 0, 0, 0, 0, 0, 1.0f);

    // 8) out = fc @ W_proj + b_proj -> fp32 [16384,1024]
    hgemm<true, 0, false, false><<<dim3(8, 128, 1), blk, GSMEM>>>(
        fcb, wpT, b_proj, nullptr, out,
        4096, 4096, 4096, 1024, 0, 0, 0, 0, 0, 1.0f);
}

// round 10
// speedup vs baseline: 1.1911x; 1.0149x over previous
#include <cuda_runtime.h>
#include <cuda_fp16.h>
#include <math.h>
#include <stdint.h>

#define D_MODEL 1024
#define B_SZ    8
#define S_LEN   2048
#define ROWS    (B_SZ * S_LEN)   /* 16384 */

// ---------------- scratch (device globals) ----------------
__device__ __half g_h16[(size_t)ROWS * D_MODEL];
__device__ __half g_qkv16[(size_t)ROWS * 3 * D_MODEL];
__device__ __half g_sc16[(size_t)B_SZ * S_LEN * S_LEN];
__device__ __half g_x2h[(size_t)ROWS * D_MODEL];
__device__ __half g_fc16[(size_t)ROWS * 4 * D_MODEL];
__device__ __half g_waT16[(size_t)3072 * 1024];
__device__ __half g_wfT16[(size_t)4096 * 1024];
__device__ __half g_wpT16[(size_t)1024 * 4096];

// ---------------- helpers ----------------
__device__ __forceinline__ float gelu_exact(float x) {
    return 0.5f * x * (1.0f + erff(x * 0.70710678118654752f));
}
__device__ __forceinline__ float block_sum(float v) {
    __shared__ float sh[8];
    int lane = threadIdx.x & 31, w = threadIdx.x >> 5;
    #pragma unroll
    for (int o = 16; o; o >>= 1) v += __shfl_xor_sync(0xffffffffu, v, o);
    if (lane == 0) sh[w] = v;
    __syncthreads();
    if (w == 0) {
        v = sh[lane & 7];
        #pragma unroll
        for (int o = 4; o; o >>= 1) v += __shfl_xor_sync(0xffffffffu, v, o);
        if (lane == 0) sh[0] = v;
    }
    __syncthreads();
    float r = sh[0];
    __syncthreads();
    return r;
}
__device__ __forceinline__ float block_max(float v) {
    __shared__ float sh[8];
    int lane = threadIdx.x & 31, w = threadIdx.x >> 5;
    #pragma unroll
    for (int o = 16; o; o >>= 1) v = fmaxf(v, __shfl_xor_sync(0xffffffffu, v, o));
    if (lane == 0) sh[w] = v;
    __syncthreads();
    if (w == 0) {
        v = sh[lane & 7];
        #pragma unroll
        for (int o = 4; o; o >>= 1) v = fmaxf(v, __shfl_xor_sync(0xffffffffu, v, o));
        if (lane == 0) sh[0] = v;
    }
    __syncthreads();
    float r = sh[0];
    __syncthreads();
    return r;
}
__device__ __forceinline__ void cp16(uint32_t dst_smem, const void* gptr) {
    asm volatile("cp.async.ca.shared.global [%0], [%1], 16;"
                 :: "r"(dst_smem), "l"(gptr) : "memory");
}

// ---------------- LayerNorm: (fp32|fp16) in, fp16 out ----------------
template <typename TI>
__global__ void ln_kernel(const TI* __restrict__ x, const float* __restrict__ w,
                          const float* __restrict__ b, __half* __restrict__ out) {
    size_t row = blockIdx.x;
    float4 v;
    if (sizeof(TI) == 4) {
        v = ((const float4*)((const float*)x + row * D_MODEL))[threadIdx.x];
    } else {
        uint2 raw = ((const uint2*)((const __half*)x + row * D_MODEL))[threadIdx.x];
        __half2* hp = (__half2*)&raw;
        float2 a = __half22float2(hp[0]);
        float2 c = __half22float2(hp[1]);
        v.x = a.x; v.y = a.y; v.z = c.x; v.w = c.y;
    }
    float s  = v.x + v.y + v.z + v.w;
    float ss = v.x * v.x + v.y * v.y + v.z * v.z + v.w * v.w;
    s  = block_sum(s);
    ss = block_sum(ss);
    float mu  = s * (1.0f / D_MODEL);
    float var = ss * (1.0f / D_MODEL) - mu * mu;
    float inv = rsqrtf(var + 1e-5f);
    float4 wv = ((const float4*)w)[threadIdx.x];
    float4 bv = ((const float4*)b)[threadIdx.x];
    __half2 o0 = __floats2half2_rn((v.x - mu) * inv * wv.x + bv.x,
                                   (v.y - mu) * inv * wv.y + bv.y);
    __half2 o1 = __floats2half2_rn((v.z - mu) * inv * wv.z + bv.z,
                                   (v.w - mu) * inv * wv.w + bv.w);
    __half2* po = (__half2*)(out + row * D_MODEL + threadIdx.x * 4);
    po[0] = o0; po[1] = o1;
}

// ---------------- Softmax over fp16 row of 2048, in-place ----------------
__global__ void softmax_kernel(__half* __restrict__ sc) {
    size_t row = blockIdx.x;
    __half* p = sc + row * (size_t)S_LEN;
    uint4 raw = ((uint4*)p)[threadIdx.x];
    __half2* hp = (__half2*)&raw;
    float f[8];
    #pragma unroll
    for (int i = 0; i < 4; i++) {
        float2 t = __half22float2(hp[i]);
        f[2 * i] = t.x; f[2 * i + 1] = t.y;
    }
    float m = f[0];
    #pragma unroll
    for (int i = 1; i < 8; i++) m = fmaxf(m, f[i]);
    m = block_max(m);
    float s = 0.0f;
    #pragma unroll
    for (int i = 0; i < 8; i++) { f[i] = expf(f[i] - m); s += f[i]; }
    s = block_sum(s);
    float inv = 1.0f / s;
    #pragma unroll
    for (int i = 0; i < 4; i++)
        hp[i] = __floats2half2_rn(f[2 * i] * inv, f[2 * i + 1] * inv);
    ((uint4*)p)[threadIdx.x] = raw;
}

// ---------------- transpose: dst[c][r] = (TO)src[r][c] ----------------
template <typename TI, typename TO>
__global__ void transpose_kernel(const TI* __restrict__ src, TO* __restrict__ dst,
                                 int lds, int ldd) {
    __shared__ float t[32][33];
    int bx = blockIdx.x * 32;
    int by = blockIdx.y * 32;
    int tx = threadIdx.x, ty = threadIdx.y;
    #pragma unroll
    for (int i = 0; i < 4; i++)
        t[ty + i * 8][tx] = (float)src[(size_t)(by + ty + i * 8) * lds + bx + tx];
    __syncthreads();
    #pragma unroll
    for (int i = 0; i < 4; i++)
        dst[(size_t)(bx + ty + i * 8) * ldd + by + tx] = (TO)t[tx][ty + i * 8];
}

// =================== fp16 mma.sync GEMM, 128x128x32, 3-stage, occ 2 ========
// C = act(alpha * A @ op(B) + bias) (+ residual)
// A [M,K] fp16 row-major.
// TRANSB=0: B [N,K] row-major (K-major), normal ldmatrix.
// TRANSB=1: B [K,N] row-major (N-major), ldmatrix.trans (e.g. V in qkv).
#define LDH 40                         /* A: 32 + 8 pad halves; 80 B stride */
#define LDBT 136                       /* trans-B: 128 + 8 pad; 272 B stride */
#define NSTAGE 3
#define A_BYTES (128 * LDH * 2)        /* 10240 */
#define BN_BYTES (128 * LDH * 2)       /* 10240: [n][k] */
#define BT_BYTES (32 * LDBT * 2)       /* 8704:  [k][n] */

template <bool TRANSB, bool BIAS, int ACT, bool RES, bool OUT16>
__global__ __launch_bounds__(256, 2)
void hgemm(const __half* __restrict__ A, const __half* __restrict__ B,
           const float* __restrict__ bias, const float* __restrict__ res,
           void* __restrict__ Cv,
           int K, int lda, int ldb, int ldc, int ldres,
           size_t sA, size_t sB, size_t sC, size_t sR, float alpha) {
    constexpr int B_BYTES = TRANSB ? BT_BYTES : BN_BYTES;
    constexpr int STAGE_BYTES = A_BYTES + B_BYTES;

    extern __shared__ char dsm[];
    const uint32_t sbase = (uint32_t)__cvta_generic_to_shared(dsm);

    const int bn = blockIdx.x, bm = blockIdx.y, bz = blockIdx.z;
    const __half* Ab = A + sA * bz + (size_t)bm * 128 * lda;
    // TRANSB: base has no row offset for bn (bn offsets columns)
    const __half* Bb = TRANSB ? (B + sB * bz + (size_t)bn * 128)
                              : (B + sB * bz + (size_t)bn * 128 * ldb);

    const int tid  = threadIdx.x;
    const int lane = tid & 31;
    const int warp = tid >> 5;
    const int wm   = warp >> 1;   // 0..3 -> 32-row slice
    const int wn   = warp & 1;    // 0..1 -> 64-col slice

    // ldmatrix lane byte-offsets
    const uint32_t a_off = (uint32_t)((lane & 15) * 80 + (lane >> 4) * 16);
    // non-trans B ([n][k], 80B rows)
    const uint32_t bn_row = (uint32_t)(((lane >> 4) << 3) + (lane & 7));
    const uint32_t bn_off = (uint32_t)(bn_row * 80 + ((lane >> 3) & 1) * 16);
    // trans B ([k][n], 272B rows): k row = lane&15, n byte = (lane>>4)*16
    const uint32_t bt_off = (uint32_t)((lane & 15) * 272 + (lane >> 4) * 16);

    float acc[2][8][4];
    #pragma unroll
    for (int i = 0; i < 2; i++)
        #pragma unroll
        for (int j = 0; j < 8; j++)
            #pragma unroll
            for (int l = 0; l < 4; l++) acc[i][j][l] = 0.0f;

    const int T = K >> 5;

    auto stage = [&](int kt, int s) {
        const int k0 = kt << 5;
        const uint32_t sa = sbase + s * STAGE_BYTES;
        const uint32_t sb = sa + A_BYTES;
        const __half* gA = Ab + (size_t)(tid >> 1) * lda + k0 + (tid & 1) * 16;
        const uint32_t dA = sa + (tid >> 1) * 80 + (tid & 1) * 32;
        cp16(dA, gA);
        cp16(dA + 16, gA + 8);
        if (TRANSB) {
            // [k32][n128]: thread t -> k row t>>3, 2 chunks of 16B at (t&7)*32
            const int kr = tid >> 3;
            const __half* gB = Bb + (size_t)(k0 + kr) * ldb + (tid & 7) * 16;
            const uint32_t dB = sb + kr * 272 + (tid & 7) * 32;
            cp16(dB, gB);
            cp16(dB + 16, gB + 8);
        } else {
            const __half* gB = Bb + (size_t)(tid >> 1) * ldb + k0 + (tid & 1) * 16;
            const uint32_t dB = sb + (tid >> 1) * 80 + (tid & 1) * 32;
            cp16(dB, gB);
            cp16(dB + 16, gB + 8);
        }
    };

    #pragma unroll
    for (int s = 0; s < NSTAGE; s++) {
        if (s < T) stage(s, s);
        asm volatile("cp.async.commit_group;" ::: "memory");
    }

    int buf = 0;
    for (int kt = 0; kt < T; kt++) {
        asm volatile("cp.async.wait_group %0;" :: "n"(NSTAGE - 1) : "memory");
        __syncthreads();

        const uint32_t sa = sbase + buf * STAGE_BYTES;
        const uint32_t sb = sa + A_BYTES;

        #pragma unroll
        for (int ks = 0; ks < 2; ks++) {
            uint32_t a[2][4];
            #pragma unroll
            for (int am = 0; am < 2; am++) {
                uint32_t addr = sa + (uint32_t)((wm * 32 + am * 16) * 80)
                              + a_off + ks * 32;
                asm volatile(
                    "ldmatrix.sync.aligned.m8n8.x4.shared.b16 {%0,%1,%2,%3}, [%4];"
                    : "=r"(a[am][0]), "=r"(a[am][1]), "=r"(a[am][2]), "=r"(a[am][3])
                    : "r"(addr));
            }
            uint32_t b[8][2];
            #pragma unroll
            for (int t = 0; t < 4; t++) {
                uint32_t r0, r1, r2, r3;
                if (TRANSB) {
                    // k rows ks*16.., n cols wn*64 + t*16..
                    uint32_t addr = sb + (uint32_t)(ks * 16 * 272)
                                  + (uint32_t)((wn * 64 + t * 16) * 2) + bt_off;
                    asm volatile(
                        "ldmatrix.sync.aligned.m8n8.x4.trans.shared.b16 {%0,%1,%2,%3}, [%4];"
                        : "=r"(r0), "=r"(r1), "=r"(r2), "=r"(r3)
                        : "r"(addr));
                } else {
                    uint32_t addr = sb + (uint32_t)((wn * 64 + t * 16) * 80)
                                  + bn_off + ks * 32;
                    asm volatile(
                        "ldmatrix.sync.aligned.m8n8.x4.shared.b16 {%0,%1,%2,%3}, [%4];"
                        : "=r"(r0), "=r"(r1), "=r"(r2), "=r"(r3)
                        : "r"(addr));
                }
                b[2 * t][0] = r0; b[2 * t][1] = r1;
                b[2 * t + 1][0] = r2; b[2 * t + 1][1] = r3;
            }
            #pragma unroll
            for (int am = 0; am < 2; am++)
                #pragma unroll
                for (int an = 0; an < 8; an++) {
                    asm volatile(
                        "mma.sync.aligned.m16n8k16.row.col.f32.f16.f16.f32 "
                        "{%0,%1,%2,%3}, {%4,%5,%6,%7}, {%8,%9}, {%0,%1,%2,%3};"
                        : "+f"(acc[am][an][0]), "+f"(acc[am][an][1]),
                          "+f"(acc[am][an][2]), "+f"(acc[am][an][3])
                        : "r"(a[am][0]), "r"(a[am][1]), "r"(a[am][2]), "r"(a[am][3]),
                          "r"(b[an][0]), "r"(b[an][1]));
                }
        }
        __syncthreads();
        if (kt + NSTAGE < T) stage(kt + NSTAGE, buf);
        asm volatile("cp.async.commit_group;" ::: "memory");
        buf = (buf + 1 == NSTAGE) ? 0 : buf + 1;
    }

    // ---- epilogue ----
    const int q  = lane >> 2;
    const int r2 = (lane & 3) * 2;
    #pragma unroll
    for (int am = 0; am < 2; am++) {
        int row0 = bm * 128 + wm * 32 + am * 16 + q;
        int row1 = row0 + 8;
        #pragma unroll
        for (int an = 0; an < 8; an++) {
            int col = bn * 128 + wn * 64 + an * 8 + r2;
            float v00 = acc[am][an][0] * alpha;
            float v01 = acc[am][an][1] * alpha;
            float v10 = acc[am][an][2] * alpha;
            float v11 = acc[am][an][3] * alpha;
            if (BIAS) {
                float2 bv = *(const float2*)(bias + col);
                v00 += bv.x; v01 += bv.y; v10 += bv.x; v11 += bv.y;
            }
            if (ACT == 1) {
                v00 = gelu_exact(v00); v01 = gelu_exact(v01);
                v10 = gelu_exact(v10); v11 = gelu_exact(v11);
            }
            if (RES) {
                float2 r0 = *(const float2*)(res + sR * bz + (size_t)row0 * ldres + col);
                float2 r1 = *(const float2*)(res + sR * bz + (size_t)row1 * ldres + col);
                v00 += r0.x; v01 += r0.y; v10 += r1.x; v11 += r1.y;
            }
            if (OUT16) {
                __half* Cb = (__half*)Cv + sC * bz;
                *(__half2*)(Cb + (size_t)row0 * ldc + col) = __floats2half2_rn(v00, v01);
                *(__half2*)(Cb + (size_t)row1 * ldc + col) = __floats2half2_rn(v10, v11);
            } else {
                float* Cb = (float*)Cv + sC * bz;
                *(float2*)(Cb + (size_t)row0 * ldc + col) = make_float2(v00, v01);
                *(float2*)(Cb + (size_t)row1 * ldc + col) = make_float2(v10, v11);
            }
        }
    }
}

#define GSMEM_N (NSTAGE * (A_BYTES + BN_BYTES))   /* 61440 */
#define GSMEM_T (NSTAGE * (A_BYTES + BT_BYTES))   /* 56832 */

// ---------------- launch ----------------
extern "C" void kernel_launch(void* const* d_in, const int* in_sizes, int n_in,
                              void* d_out, int out_size) {
    const float* x      = (const float*)d_in[0];
    const float* ln1_w  = (const float*)d_in[1];
    const float* ln1_b  = (const float*)d_in[2];
    const float* W_attn = (const float*)d_in[3];
    const float* b_attn = (const float*)d_in[4];
    const float* ln2_w  = (const float*)d_in[5];
    const float* ln2_b  = (const float*)d_in[6];
    const float* W_fc   = (const float*)d_in[7];
    const float* b_fc   = (const float*)d_in[8];
    const float* W_proj = (const float*)d_in[9];
    const float* b_proj = (const float*)d_in[10];
    float* out = (float*)d_out;

    void* p;
    cudaGetSymbolAddress(&p, g_h16);    __half* h    = (__half*)p;
    cudaGetSymbolAddress(&p, g_qkv16);  __half* qkv  = (__half*)p;
    cudaGetSymbolAddress(&p, g_sc16);   __half* sc   = (__half*)p;
    cudaGetSymbolAddress(&p, g_x2h);    __half* x2   = (__half*)p;
    cudaGetSymbolAddress(&p, g_fc16);   __half* fcb  = (__half*)p;
    cudaGetSymbolAddress(&p, g_waT16);  __half* waT  = (__half*)p;
    cudaGetSymbolAddress(&p, g_wfT16);  __half* wfT  = (__half*)p;
    cudaGetSymbolAddress(&p, g_wpT16);  __half* wpT  = (__half*)p;

    cudaFuncSetAttribute(hgemm<false, true, 0, false, true>,
                         cudaFuncAttributeMaxDynamicSharedMemorySize, GSMEM_N);
    cudaFuncSetAttribute(hgemm<false, false, 0, false, true>,
                         cudaFuncAttributeMaxDynamicSharedMemorySize, GSMEM_N);
    cudaFuncSetAttribute(hgemm<true, false, 0, true, true>,
                         cudaFuncAttributeMaxDynamicSharedMemorySize, GSMEM_T);
    cudaFuncSetAttribute(hgemm<false, true, 1, false, true>,
                         cudaFuncAttributeMaxDynamicSharedMemorySize, GSMEM_N);
    cudaFuncSetAttribute(hgemm<false, true, 0, false, false>,
                         cudaFuncAttributeMaxDynamicSharedMemorySize, GSMEM_N);

    dim3 blk(256);
    dim3 tblk(32, 8);

    // weight transposes -> K-major fp16
    transpose_kernel<float, __half><<<dim3(96, 32), tblk>>>(W_attn, waT, 3072, 1024);
    transpose_kernel<float, __half><<<dim3(128, 32), tblk>>>(W_fc, wfT, 4096, 1024);
    transpose_kernel<float, __half><<<dim3(32, 128), tblk>>>(W_proj, wpT, 1024, 4096);

    // 1) h = LN1(x) -> fp16
    ln_kernel<float><<<ROWS, blk>>>(x, ln1_w, ln1_b, h);

    // 2) qkv = h @ W_attn + b_attn -> fp16 [16384,3072]
    hgemm<false, true, 0, false, true><<<dim3(24, 128, 1), blk, GSMEM_N>>>(
        h, waT, b_attn, nullptr, qkv,
        1024, 1024, 1024, 3072, 0, 0, 0, 0, 0, 1.0f);

    // 3) scores = (q @ k^T)/sqrt(D) -> fp16
    hgemm<false, false, 0, false, true><<<dim3(16, 16, 8), blk, GSMEM_N>>>(
        qkv, qkv + 1024, nullptr, nullptr, sc,
        1024, 3072, 3072, 2048, 0,
        (size_t)S_LEN * 3072, (size_t)S_LEN * 3072, (size_t)S_LEN * S_LEN, 0,
        0.03125f);

    // 4) softmax (fp16 in/out)
    softmax_kernel<<<ROWS, blk>>>(sc);

    // 5) x2 = x + attn @ V  -> fp16   (trans-B: V = qkv[:, 2048:] as [K,N])
    hgemm<true, false, 0, true, true><<<dim3(8, 16, 8), blk, GSMEM_T>>>(
        sc, qkv + 2048, nullptr, x, x2,
        2048, 2048, 3072, 1024, 1024,
        (size_t)S_LEN * S_LEN, (size_t)S_LEN * 3072,
        (size_t)S_LEN * 1024, (size_t)S_LEN * 1024, 1.0f);

    // 6) h = LN2(x2) -> fp16  (fp16 input)
    ln_kernel<__half><<<ROWS, blk>>>(x2, ln2_w, ln2_b, h);

    // 7) fc = gelu(h @ W_fc + b_fc) -> fp16 [16384,4096]
    hgemm<false, true, 1, false, true><<<dim3(32, 128, 1), blk, GSMEM_N>>>(
        h, wfT, b_fc, nullptr, fcb,
        1024, 1024, 1024, 4096, 0, 0, 0, 0, 0, 1.0f);

    // 8) out = fc @ W_proj + b_proj -> fp32 [16384,1024]
    hgemm<false, true, 0, false, false><<<dim3(8, 128, 1), blk, GSMEM_N>>>(
        fcb, wpT, b_proj, nullptr, out,
        4096, 4096, 4096, 1024, 0, 0, 0, 0, 0, 1.0f);
}